// round 12
// baseline (speedup 1.0000x reference)
#include <cuda_runtime.h>
#include <cuda_bf16.h>
#include <cstdint>

#define CCH 64
#define CO 8
#define WIN 13
#define TP 104
#define HPOS 52          // positions per half = 4 complete windows
#define NVOX 53248
#define TILES_PER_B 512
#define NTHREADS 256

#define APB 272          // A row pitch bytes: [hi 128B | lo 128B | 16 pad]
#define BPB 112          // B row pitch bytes (56 bf16 slots; cols 52-55 zero)
#define ZSPH 60          // z pitch words (60 % 16 == 12 -> bank-distinct patterns)
#define QKP 12           // qT/kT row pitch words
#define QROWS 56         // qT/kT rows (gp can reach 55)
#define ARP 16           // att row pitch words
#define AWS 212          // att window stride words (distinct banks across pt)

// smem byte offsets (total 57152 -> 4 CTAs/SM)
#define OFF_A    0       // 80*272 = 21760
#define OFF_BH   21760   // 64*112 = 7168
#define OFF_BL   28928   // 7168 -> 36096
#define OFF_ATT  21760   // 4*212*4 = 3392 (aliases B; live only scores->apply)
#define OFF_Z    36096   // 64*60*4 = 15360 -> 51456 (also the staged out buffer)
#define OFF_QT   51456   // 56*12*4 = 2688
#define OFF_KT   54144   // 2688 -> 56832
#define OFF_BQ   56832
#define OFF_BK   56864
#define OFF_BV   56896   // 256 -> 57152
#define SMEM_BYTES 57152

typedef unsigned long long u64;

__device__ __forceinline__ u64 fma2(u64 a, u64 b, u64 c) {
    u64 d; asm("fma.rn.f32x2 %0, %1, %2, %3;" : "=l"(d) : "l"(a), "l"(b), "l"(c));
    return d;
}
__device__ __forceinline__ u64 mul2(u64 a, u64 b) {
    u64 d; asm("mul.rn.f32x2 %0, %1, %2;" : "=l"(d) : "l"(a), "l"(b));
    return d;
}
__device__ __forceinline__ u64 pack2(float lo, float hi) {
    u64 d; asm("mov.b64 %0, {%1, %2};" : "=l"(d) : "f"(lo), "f"(hi));
    return d;
}
__device__ __forceinline__ float lo2(u64 v) { return __uint_as_float((unsigned)v); }
__device__ __forceinline__ float hi2(u64 v) { return __uint_as_float((unsigned)(v >> 32)); }

__device__ __forceinline__ uint32_t smem_u32(const void* p) {
    uint32_t a;
    asm("{ .reg .u64 t; cvta.to.shared.u64 t, %1; cvt.u32.u64 %0, t; }" : "=r"(a) : "l"(p));
    return a;
}
__device__ __forceinline__ void ldsm4(uint32_t* r, uint32_t addr) {
    asm volatile("ldmatrix.sync.aligned.m8n8.x4.shared.b16 {%0,%1,%2,%3}, [%4];"
                 : "=r"(r[0]), "=r"(r[1]), "=r"(r[2]), "=r"(r[3]) : "r"(addr));
}
__device__ __forceinline__ void ldsm4t(uint32_t* r, uint32_t addr) {
    asm volatile("ldmatrix.sync.aligned.m8n8.x4.trans.shared.b16 {%0,%1,%2,%3}, [%4];"
                 : "=r"(r[0]), "=r"(r[1]), "=r"(r[2]), "=r"(r[3]) : "r"(addr));
}
__device__ __forceinline__ void mma16816(float* d, const uint32_t* a, const uint32_t* b) {
    asm volatile(
        "mma.sync.aligned.m16n8k16.row.col.f32.bf16.bf16.f32 "
        "{%0,%1,%2,%3}, {%4,%5,%6,%7}, {%8,%9}, {%0,%1,%2,%3};"
        : "+f"(d[0]), "+f"(d[1]), "+f"(d[2]), "+f"(d[3])
        : "r"(a[0]), "r"(a[1]), "r"(a[2]), "r"(a[3]), "r"(b[0]), "r"(b[1]));
}
__device__ __forceinline__ void split_pack(float v0, float v1, float v2, float v3,
                                           uint2& hp, uint2& lp) {
    __nv_bfloat16 h0 = __float2bfloat16(v0), h1 = __float2bfloat16(v1);
    __nv_bfloat16 h2 = __float2bfloat16(v2), h3 = __float2bfloat16(v3);
    __nv_bfloat16 l0 = __float2bfloat16(v0 - __bfloat162float(h0));
    __nv_bfloat16 l1 = __float2bfloat16(v1 - __bfloat162float(h1));
    __nv_bfloat16 l2 = __float2bfloat16(v2 - __bfloat162float(h2));
    __nv_bfloat16 l3 = __float2bfloat16(v3 - __bfloat162float(h3));
    hp.x = (unsigned)__bfloat16_as_ushort(h0) | ((unsigned)__bfloat16_as_ushort(h1) << 16);
    hp.y = (unsigned)__bfloat16_as_ushort(h2) | ((unsigned)__bfloat16_as_ushort(h3) << 16);
    lp.x = (unsigned)__bfloat16_as_ushort(l0) | ((unsigned)__bfloat16_as_ushort(l1) << 16);
    lp.y = (unsigned)__bfloat16_as_ushort(l2) | ((unsigned)__bfloat16_as_ushort(l3) << 16);
}

// One (m, nt-group) GEMM unit; compile-time NT so everything unrolls.
template<int NT>
__device__ __forceinline__ void gemm_unit(
    const uint32_t sb, char* smem, int m, int ntBeg, int lid)
{
    float* s_z  = (float*)(smem + OFF_Z);
    float* s_qT = (float*)(smem + OFF_QT);
    float* s_kT = (float*)(smem + OFF_KT);
    float* s_bq = (float*)(smem + OFF_BQ);
    float* s_bk = (float*)(smem + OFF_BK);

    float d[NT * 4];
#pragma unroll
    for (int i = 0; i < NT * 4; i++) d[i] = 0.f;

    const uint32_t aaddr = sb + OFF_A + (uint32_t)(lid & 15) * APB
                         + (uint32_t)(lid & 16) + (uint32_t)(16 * m) * APB;

#pragma unroll
    for (int ktp = 0; ktp < 2; ktp++) {
        uint32_t ah[8], al[8];
        ldsm4(ah,     aaddr + ktp * 64);
        ldsm4(ah + 4, aaddr + ktp * 64 + 32);
        ldsm4(al,     aaddr + 128 + ktp * 64);
        ldsm4(al + 4, aaddr + 128 + ktp * 64 + 32);
        uint32_t brow = sb + (uint32_t)(ktp * 32 + lid) * BPB;
#pragma unroll
        for (int j = 0; j < NT; j++) {
            int nt = ntBeg + j;
            uint32_t bh[4], bl[4];
            ldsm4t(bh, brow + OFF_BH + nt * 16);
            ldsm4t(bl, brow + OFF_BL + nt * 16);
            float* dj = d + 4 * j;
            mma16816(dj, ah,     bh);
            mma16816(dj, ah,     bl);
            mma16816(dj, al,     bh);
            mma16816(dj, ah + 4, bh + 2);
            mma16816(dj, ah + 4, bl + 2);
            mma16816(dj, al + 4, bh + 2);
        }
    }

    int r = lid >> 2;
#pragma unroll
    for (int j = 0; j < NT; j++) {
        int nt = ntBeg + j;
        int gp = nt * 8 + 2 * (lid & 3);
        float* dj = d + 4 * j;
        if (m < 4) {
            *(float2*)(s_z + (16 * m + r) * ZSPH + gp)     = make_float2(dj[0], dj[1]);
            *(float2*)(s_z + (16 * m + r + 8) * ZSPH + gp) = make_float2(dj[2], dj[3]);
        } else {
            float bqv = s_bq[r], bkv = s_bk[r];
            s_qT[gp * QKP + r]       = dj[0] + bqv;
            s_qT[(gp + 1) * QKP + r] = dj[1] + bqv;
            s_kT[gp * QKP + r]       = dj[2] + bkv;
            s_kT[(gp + 1) * QKP + r] = dj[3] + bkv;
        }
    }
}

__global__ __launch_bounds__(NTHREADS, 4)
void win_attn_kernel(const float* __restrict__ x,
                     const float* __restrict__ wq, const float* __restrict__ bq,
                     const float* __restrict__ wk, const float* __restrict__ bk,
                     const float* __restrict__ wv, const float* __restrict__ bv,
                     float* __restrict__ out) {
    extern __shared__ char smem[];
    const uint32_t sb = smem_u32(smem);
    float* s_z   = (float*)(smem + OFF_Z);
    float* s_qT  = (float*)(smem + OFF_QT);
    float* s_kT  = (float*)(smem + OFF_KT);
    float* s_att = (float*)(smem + OFF_ATT);
    float* s_bq  = (float*)(smem + OFF_BQ);
    float* s_bk  = (float*)(smem + OFF_BK);
    float* s_bv  = (float*)(smem + OFF_BV);

    const int tid = threadIdx.x;
    const int wid = tid >> 5;
    const int lid = tid & 31;

    const int b    = blockIdx.x / TILES_PER_B;
    const int tile = blockIdx.x % TILES_PER_B;
    const long n0  = (long)tile * TP;
    const float* xb = x   + (long)b * CCH * NVOX + n0;
    float*       ob = out + (long)b * CCH * NVOX + n0;

    // ---- prologue: A = [wv;wq;wk] (80x64) bf16 hi|lo, pitch 272B ----
    for (int f = tid; f < 80 * 16; f += NTHREADS) {
        int row = f >> 4, c4 = f & 15;
        const float* src = (row < 64) ? (wv + row * 64 + c4 * 4)
                         : (row < 72) ? (wq + (row - 64) * 64 + c4 * 4)
                                      : (wk + (row - 72) * 64 + c4 * 4);
        float4 v = *(const float4*)src;
        uint2 hp, lp;
        split_pack(v.x, v.y, v.z, v.w, hp, lp);
        *(uint2*)(smem + OFF_A + row * APB + c4 * 8) = hp;
        *(uint2*)(smem + OFF_A + row * APB + 128 + c4 * 8) = lp;
    }
    // zero B pad cols 52-55 (hi & lo), written once, never refilled
    if (tid < 128) {
        int row = tid & 63, buf = tid >> 6;
        *(u64*)(smem + (buf ? OFF_BL : OFF_BH) + row * BPB + 104) = 0ull;
    }
    // biases
    if (tid < CO)                      s_bq[tid]       = bq[tid];
    if (tid >= 64 && tid < 64 + CO)    s_bk[tid - 64]  = bk[tid - 64];
    if (tid >= 128 && tid < 128 + CCH) s_bv[tid - 128] = bv[tid - 128];

    const int mA = wid >> 1;
    const int ng = wid & 1;

    for (int h = 0; h < 2; h++) {
        // ---- fill B: x [ch][pos 0..51] bf16 hi/lo ----
        for (int f = tid; f < CCH * 13; f += NTHREADS) {
            int ch = f / 13, p4 = f % 13;
            float4 v = *(const float4*)(xb + (long)ch * NVOX + h * HPOS + p4 * 4);
            uint2 hp, lp;
            split_pack(v.x, v.y, v.z, v.w, hp, lp);
            *(uint2*)(smem + OFF_BH + ch * BPB + p4 * 8) = hp;
            *(uint2*)(smem + OFF_BL + ch * BPB + p4 * 8) = lp;
        }
        __syncthreads();

        // ---- GEMM: D(80x52) = Ah Bh + Ah Bl + Al Bh ----
        if (wid == 0) {
            gemm_unit<4>(sb, smem, 0, 0, lid);
            gemm_unit<4>(sb, smem, 4, 0, lid);
        } else if (wid == 1) {
            gemm_unit<3>(sb, smem, 0, 4, lid);
            gemm_unit<3>(sb, smem, 4, 4, lid);
        } else if (ng == 0) {
            gemm_unit<4>(sb, smem, mA, 0, lid);
        } else {
            gemm_unit<3>(sb, smem, mA, 4, lid);
        }
        __syncthreads();

        // ---- scores: 4 windows x 13x13, packed dot over 8 q/k channels ----
        for (int m = tid; m < 4 * WIN * WIN; m += NTHREADS) {
            int w  = m / (WIN * WIN);
            int ij = m % (WIN * WIN);
            int ii = ij / WIN, jj = ij % WIN;
            ulonglong2 qa = *(const ulonglong2*)&s_qT[(w * WIN + ii) * QKP];
            ulonglong2 qb = *(const ulonglong2*)&s_qT[(w * WIN + ii) * QKP + 4];
            ulonglong2 ka = *(const ulonglong2*)&s_kT[(w * WIN + jj) * QKP];
            ulonglong2 kb = *(const ulonglong2*)&s_kT[(w * WIN + jj) * QKP + 4];
            u64 acc = fma2(qa.x, ka.x,
                      fma2(qa.y, ka.y,
                      fma2(qb.x, kb.x,
                      mul2(qb.y, kb.y))));
            s_att[w * AWS + ii * ARP + jj] = lo2(acc) + hi2(acc);
        }
        __syncthreads();

        // ---- softmax over 52 rows of length 13 ----
        if (tid < HPOS) {
            int w = tid / WIN, ii = tid % WIN;
            float* row = &s_att[w * AWS + ii * ARP];
            float4 ra = *(const float4*)row;
            float4 rb = *(const float4*)(row + 4);
            float4 rc = *(const float4*)(row + 8);
            float  rd = row[12];
            float m0 = fmaxf(fmaxf(fmaxf(ra.x, ra.y), fmaxf(ra.z, ra.w)),
                       fmaxf(fmaxf(fmaxf(rb.x, rb.y), fmaxf(rb.z, rb.w)),
                       fmaxf(fmaxf(fmaxf(rc.x, rc.y), fmaxf(rc.z, rc.w)), rd)));
            ra.x = __expf(ra.x - m0); ra.y = __expf(ra.y - m0);
            ra.z = __expf(ra.z - m0); ra.w = __expf(ra.w - m0);
            rb.x = __expf(rb.x - m0); rb.y = __expf(rb.y - m0);
            rb.z = __expf(rb.z - m0); rb.w = __expf(rb.w - m0);
            rc.x = __expf(rc.x - m0); rc.y = __expf(rc.y - m0);
            rc.z = __expf(rc.z - m0); rc.w = __expf(rc.w - m0);
            rd   = __expf(rd   - m0);
            float sum = ra.x + ra.y + ra.z + ra.w + rb.x + rb.y + rb.z + rb.w
                      + rc.x + rc.y + rc.z + rc.w + rd;
            float inv = __frcp_rn(sum);
            ra.x *= inv; ra.y *= inv; ra.z *= inv; ra.w *= inv;
            rb.x *= inv; rb.y *= inv; rb.z *= inv; rb.w *= inv;
            rc.x *= inv; rc.y *= inv; rc.z *= inv; rc.w *= inv;
            rd   *= inv;
            *(float4*)row       = ra;
            *(float4*)(row + 4) = rb;
            *(float4*)(row + 8) = rc;
            row[12] = rd;
        }
        __syncthreads();

        // ---- apply in place: z[c][w*13..] <- z . att^T + bv ----
        {
            const int ct = tid >> 2;       // 0..63 channel
            const int pt = tid & 3;        // 0..3 window (half-local)
            float* zr = s_z + ct * ZSPH + pt * WIN;

            float z[WIN];
#pragma unroll
            for (int j = 0; j < WIN; j++) z[j] = zr[j];
            u64 zp[6];
#pragma unroll
            for (int q = 0; q < 6; q++) zp[q] = pack2(z[2*q], z[2*q + 1]);
            const float z12 = z[12];

            const float* ar = s_att + pt * AWS;
            const float bvv = s_bv[ct];
#pragma unroll
            for (int i = 0; i < WIN; i++) {
                const float* ari = ar + i * ARP;
                ulonglong2 aA = *(const ulonglong2*)ari;
                ulonglong2 aB = *(const ulonglong2*)(ari + 4);
                ulonglong2 aC = *(const ulonglong2*)(ari + 8);
                float a12 = ari[12];
                u64 s = fma2(zp[0], aA.x,
                        fma2(zp[1], aA.y,
                        fma2(zp[2], aB.x,
                        fma2(zp[3], aB.y,
                        fma2(zp[4], aC.x,
                        mul2(zp[5], aC.y))))));
                zr[i] = lo2(s) + hi2(s) + fmaf(z12, a12, bvv);
            }
        }
        __syncthreads();

        // ---- coalesced store: 64 rows x 52 floats as float4 ----
        for (int i = tid; i < CCH * 13; i += NTHREADS) {
            int r  = i / 13;
            int c4 = i % 13;
            float4 v = *(const float4*)(s_z + r * ZSPH + c4 * 4);
            *(float4*)(ob + (long)r * NVOX + h * HPOS + c4 * 4) = v;
        }
        __syncthreads();   // protect B/att (and z) before next half
    }
}

extern "C" void kernel_launch(void* const* d_in, const int* in_sizes, int n_in,
                              void* d_out, int out_size) {
    const float* x  = (const float*)d_in[0];
    const float* wq = (const float*)d_in[1];
    const float* bq = (const float*)d_in[2];
    const float* wk = (const float*)d_in[3];
    const float* bk = (const float*)d_in[4];
    const float* wv = (const float*)d_in[5];
    const float* bv = (const float*)d_in[6];
    float* out = (float*)d_out;

    const int B = in_sizes[0] / (CCH * NVOX);   // 8

    static bool attr_set = false;
    if (!attr_set) {
        cudaFuncSetAttribute(win_attn_kernel,
                             cudaFuncAttributeMaxDynamicSharedMemorySize, SMEM_BYTES);
        attr_set = true;
    }

    dim3 grid(B * TILES_PER_B);
    win_attn_kernel<<<grid, NTHREADS, SMEM_BYTES>>>(x, wq, bq, wk, bk, wv, bv, out);
}